// round 13
// baseline (speedup 1.0000x reference)
#include <cuda_runtime.h>
#include <cuda_fp16.h>
#include <cstdint>

#define T_SEQ 2048
#define NB    4
#define NHEAD 16
#define DK    64
#define DMODEL 1024
#define HDIM  1024

// Scratch (allocation-free rule: __device__ globals)
__device__ __half g_Q[NB * NHEAD * T_SEQ * DK];    // [n,h,t,d] fp16, pre-scaled
__device__ __half g_V[NB * NHEAD * T_SEQ * DK];    // [n,h,t,d] fp16
__device__ __half g_A[NB * T_SEQ * HDIM];          // [n,t,h*d] fp16
__device__ __half g_Xq[NB * T_SEQ * DMODEL];       // fp16 inputs
__device__ __half g_Xv[NB * T_SEQ * DMODEL];
__device__ __half g_WqT[DMODEL * HDIM];            // W^T fp16: [n][k]
__device__ __half g_WvT[DMODEL * HDIM];
__device__ __half g_WfT[HDIM * DMODEL];

// ---------------------------------------------------------------------------
// helpers
// ---------------------------------------------------------------------------
__device__ __forceinline__ uint32_t pack_h2(float a, float b) {
    __half2 h = __floats2half2_rn(a, b);
    return *(uint32_t*)&h;
}

// packed fp16 exp2 of two floats: {lo=exp2(lo), hi=exp2(hi)} — 1 MUFU for 2
__device__ __forceinline__ uint32_t h2exp2(float lo, float hi) {
    uint32_t r;
    asm("{\n\t.reg .b32 x;\n\t"
        "cvt.rn.f16x2.f32 x, %2, %1;\n\t"
        "ex2.approx.f16x2 %0, x;\n\t}"
        : "=r"(r) : "f"(lo), "f"(hi));
    return r;
}

__device__ __forceinline__ void mma16(float* c, const uint32_t* a, uint32_t b0, uint32_t b1) {
    asm volatile(
        "mma.sync.aligned.m16n8k16.row.col.f32.f16.f16.f32 "
        "{%0,%1,%2,%3}, {%4,%5,%6,%7}, {%8,%9}, {%0,%1,%2,%3};"
        : "+f"(c[0]), "+f"(c[1]), "+f"(c[2]), "+f"(c[3])
        : "r"(a[0]), "r"(a[1]), "r"(a[2]), "r"(a[3]), "r"(b0), "r"(b1));
}

__device__ __forceinline__ void ldsm_x4(uint32_t addr, uint32_t* r) {
    asm volatile("ldmatrix.sync.aligned.m8n8.x4.shared.b16 {%0,%1,%2,%3}, [%4];"
                 : "=r"(r[0]), "=r"(r[1]), "=r"(r[2]), "=r"(r[3]) : "r"(addr));
}
__device__ __forceinline__ void ldsm_x4t(uint32_t addr, uint32_t* r) {
    asm volatile("ldmatrix.sync.aligned.m8n8.x4.trans.shared.b16 {%0,%1,%2,%3}, [%4];"
                 : "=r"(r[0]), "=r"(r[1]), "=r"(r[2]), "=r"(r[3]) : "r"(addr));
}

__device__ __forceinline__ void cpa16(uint32_t s, const void* g) {
    asm volatile("cp.async.cg.shared.global [%0], [%1], 16;" :: "r"(s), "l"(g));
}
__device__ __forceinline__ void cpa_commit() {
    asm volatile("cp.async.commit_group;" ::: "memory");
}
template <int N>
__device__ __forceinline__ void cpa_wait() {
    asm volatile("cp.async.wait_group %0;" :: "n"(N) : "memory");
}
__device__ __forceinline__ uint32_t sm_u32(const void* p) {
    return (uint32_t)__cvta_generic_to_shared(p);
}

// ---------------------------------------------------------------------------
// prep: fp32 -> fp16 (both inputs in one launch, z selects)
// ---------------------------------------------------------------------------
__global__ void cvtX2(const float4* __restrict__ inq, const float4* __restrict__ inv,
                      uint2* __restrict__ outq, uint2* __restrict__ outv, int n4) {
    const float4* in = blockIdx.y ? inv : inq;
    uint2* out = blockIdx.y ? outv : outq;
    int i = blockIdx.x * blockDim.x + threadIdx.x;
    if (i < n4) {
        float4 v = in[i];
        out[i] = make_uint2(pack_h2(v.x, v.y), pack_h2(v.z, v.w));
    }
}

// out[n][k] = half(in[k][n]); three 1024x1024 matrices selected by blockIdx.z
__global__ __launch_bounds__(256)
void cvtW3(const float* __restrict__ W0, const float* __restrict__ W1,
           const float* __restrict__ W2, __half* __restrict__ O0,
           __half* __restrict__ O1, __half* __restrict__ O2)
{
    const float* in = (blockIdx.z == 0) ? W0 : (blockIdx.z == 1) ? W1 : W2;
    __half* out = (blockIdx.z == 0) ? O0 : (blockIdx.z == 1) ? O1 : O2;
    __shared__ float t[32][33];
    const int x = blockIdx.x * 32 + threadIdx.x;
    const int y0 = blockIdx.y * 32;
#pragma unroll
    for (int i = threadIdx.y; i < 32; i += 8)
        t[i][threadIdx.x] = in[(size_t)(y0 + i) * HDIM + x];
    __syncthreads();
    const int ox = blockIdx.y * 32 + threadIdx.x;
    const int oy0 = blockIdx.x * 32;
#pragma unroll
    for (int i = threadIdx.y; i < 32; i += 8)
        out[(size_t)(oy0 + i) * DMODEL + ox] = __float2half_rn(t[threadIdx.x][i]);
}

// ---------------------------------------------------------------------------
// fp16 GEMM (m16n8k16): EXACT R10 config (proven best: 66.5us).
// CTA 128x128, 256 threads, 8 warps 4m x 2n, k64 chunks, 3-stage cp.async.
// ---------------------------------------------------------------------------
#define AW 36                       // half2 words per k64 row (32 data + 4 pad)
#define STW (128 * AW)
#define NSTG 3
#define GEMM_SMEM (NSTG * 2 * STW * 4)   // 110592 B

__global__ __launch_bounds__(256, 2)
void gemm_f16(const __half* __restrict__ X, const __half* __restrict__ Wt,
              const float* __restrict__ bias, float* __restrict__ Cf,
              __half* __restrict__ Ch, int headsplit, float oscale)
{
    extern __shared__ uint32_t sm[];

    const int tid = threadIdx.x;
    const int lane = tid & 31;
    const int warp = tid >> 5;
    const int g = lane >> 2;
    const int t = lane & 3;
    const int wm = warp & 3;
    const int wn = warp >> 2;
    const int bm = blockIdx.y * 128;
    const int bn = blockIdx.x * 128;

    const uint32_t sBase = sm_u32(sm);
    const int lrow = (lane & 7) + ((lane >> 3) & 1) * 8;
    const int lcol = (lane >> 4) * 16;
    const uint32_t aOff0 = (uint32_t)((wm * 32 + lrow) * (AW * 4) + lcol);
    const uint32_t aOff1 = aOff0 + 16 * (AW * 4);
    uint32_t bOff[4];
#pragma unroll
    for (int n16 = 0; n16 < 4; n16++)
        bOff[n16] = (uint32_t)((wn * 64 + n16 * 16 + lrow) * (AW * 4) + lcol);

    float c[2][8][4];
#pragma unroll
    for (int mt = 0; mt < 2; mt++)
#pragma unroll
        for (int nt = 0; nt < 8; nt++)
#pragma unroll
            for (int i = 0; i < 4; i++) c[mt][nt][i] = 0.f;

#define ISSUE(stage, kk)                                                        \
    do {                                                                        \
        const uint32_t ab = sBase + (uint32_t)(stage) * 2 * STW * 4;            \
        const uint32_t bb = ab + STW * 4;                                       \
        _Pragma("unroll")                                                       \
        for (int i = 0; i < 4; i++) {                                           \
            const int idx = tid + i * 256;                                      \
            const int r = idx >> 3, h8 = (idx & 7) * 8;                         \
            cpa16(ab + (uint32_t)(r * (AW * 4) + h8 * 2),                       \
                  &X[(size_t)(bm + r) * DMODEL + (kk) + h8]);                   \
            cpa16(bb + (uint32_t)(r * (AW * 4) + h8 * 2),                       \
                  &Wt[(size_t)(bn + r) * DMODEL + (kk) + h8]);                  \
        }                                                                       \
    } while (0)

    ISSUE(0, 0);  cpa_commit();
    ISSUE(1, 64); cpa_commit();
    cpa_wait<1>();
    __syncthreads();

    const int NKT = DMODEL / 64;   // 16
    for (int kt = 0; kt < NKT; kt++) {
        const int cur = kt % NSTG;
        if (kt + 2 < NKT) ISSUE((kt + 2) % NSTG, (kt + 2) * 64);
        cpa_commit();

        const uint32_t aBase = sBase + (uint32_t)cur * 2 * STW * 4;
        const uint32_t bBase = aBase + STW * 4;

#pragma unroll
        for (int c2 = 0; c2 < 2; c2++) {
            const uint32_t co = (uint32_t)c2 * 64;
            uint32_t a[2][2][4], b[2][4][4];
#pragma unroll
            for (int ks = 0; ks < 2; ks++) {
                ldsm_x4(aBase + aOff0 + co + ks * 32, a[ks][0]);
                ldsm_x4(aBase + aOff1 + co + ks * 32, a[ks][1]);
#pragma unroll
                for (int n16 = 0; n16 < 4; n16++)
                    ldsm_x4(bBase + bOff[n16] + co + ks * 32, b[ks][n16]);
            }
#pragma unroll
            for (int ks = 0; ks < 2; ks++)
#pragma unroll
                for (int mt = 0; mt < 2; mt++)
#pragma unroll
                    for (int n16 = 0; n16 < 4; n16++) {
                        mma16(c[mt][n16 * 2 + 0], a[ks][mt], b[ks][n16][0], b[ks][n16][2]);
                        mma16(c[mt][n16 * 2 + 1], a[ks][mt], b[ks][n16][1], b[ks][n16][3]);
                    }
        }
        cpa_wait<1>();
        __syncthreads();
    }
#undef ISSUE

#pragma unroll
    for (int mt = 0; mt < 2; mt++) {
#pragma unroll
        for (int nt = 0; nt < 8; nt++) {
            const int row = bm + wm * 32 + mt * 16 + g;
            const int col = bn + wn * 64 + nt * 8 + t * 2;
            const float b0 = bias[col], b1 = bias[col + 1];
            const float v00 = c[mt][nt][0] + b0, v01 = c[mt][nt][1] + b1;
            const float v10 = c[mt][nt][2] + b0, v11 = c[mt][nt][3] + b1;
            if (!headsplit) {
                *(float2*)&Cf[(size_t)row * HDIM + col] = make_float2(v00, v01);
                *(float2*)&Cf[(size_t)(row + 8) * HDIM + col] = make_float2(v10, v11);
            } else {
                const int h = col >> 6, d = col & 63;
                const int n0 = row >> 11, t0 = row & 2047;
                const int n1 = (row + 8) >> 11, t1 = (row + 8) & 2047;
                *(uint32_t*)&Ch[(size_t)(((n0 * NHEAD + h) * T_SEQ) + t0) * DK + d] =
                    pack_h2(oscale * v00, oscale * v01);
                *(uint32_t*)&Ch[(size_t)(((n1 * NHEAD + h) * T_SEQ) + t1) * DK + d] =
                    pack_h2(oscale * v10, oscale * v11);
            }
        }
    }
}

// ---------------------------------------------------------------------------
// Flash attention, fp16 m16n8k16, register-resident P.
// R13: 128-key V staging (half the barriers; two 64-key halves per stage)
// and 4 CTAs/SM (4 independent barrier domains per SM).
// ---------------------------------------------------------------------------
#define VST 36                        // Vs row stride in half2 words (144B)
#define VROWS 128                     // rows per V buffer (one staged chunk)
#define VBUFW (VROWS * VST)
#define ATTN_SMEM (2 * VBUFW * 4 + T_SEQ * 4)   // 44800 B

__global__ __launch_bounds__(128, 4)
void attn_f16(const __half* __restrict__ Q, const __half* __restrict__ V,
              const int* __restrict__ mask, __half* __restrict__ A)
{
    extern __shared__ uint32_t sm[];
    uint32_t* Vs = sm;                        // [2][VROWS][VST]
    float* Ms = (float*)(Vs + 2 * VBUFW);     // additive mask bias [T_SEQ]

    const int tid = threadIdx.x;
    const int lane = tid & 31;
    const int warp = tid >> 5;
    const int g = lane >> 2;
    const int t = lane & 3;
    const int nh = blockIdx.y;
    const int n = nh >> 4;
    const int h = nh & 15;
    const int q0 = blockIdx.x * 128;
    const int wr = warp * 32;

    const uint32_t sVs = sm_u32(Vs);
    const uint32_t sRow = (uint32_t)((lane >> 4) * 8 + (lane & 7)) * (VST * 4)
                        + ((lane >> 3) & 1) * 16;
    const uint32_t tRow = (uint32_t)(lane & 15) * (VST * 4) + (lane >> 4) * 16;

#pragma unroll
    for (int i = 0; i < 16; i++) {
        const int j = tid + i * 128;
        Ms[j] = mask[n * T_SEQ + j] ? 0.f : -1e30f;
    }

    // Q fragments (already scaled by 0.125*log2e at projection): 4 k16-chunks
    const __half* Qp = Q + ((size_t)nh * T_SEQ + q0 + wr) * DK;
    uint32_t qa[4][2][4];
#pragma unroll
    for (int kd = 0; kd < 4; kd++)
#pragma unroll
        for (int mt = 0; mt < 2; mt++) {
            const int r0 = mt * 16 + g, r1 = r0 + 8;
            qa[kd][mt][0] = *(const uint32_t*)&Qp[r0 * DK + kd * 16 + 2 * t];
            qa[kd][mt][1] = *(const uint32_t*)&Qp[r1 * DK + kd * 16 + 2 * t];
            qa[kd][mt][2] = *(const uint32_t*)&Qp[r0 * DK + kd * 16 + 2 * t + 8];
            qa[kd][mt][3] = *(const uint32_t*)&Qp[r1 * DK + kd * 16 + 2 * t + 8];
        }

    float o[2][8][4];
#pragma unroll
    for (int mt = 0; mt < 2; mt++)
#pragma unroll
        for (int dt = 0; dt < 8; dt++)
#pragma unroll
            for (int i = 0; i < 4; i++) o[mt][dt][i] = 0.f;
    float l[2][2] = {{0.f, 0.f}, {0.f, 0.f}};

    const __half* Vp = V + (size_t)nh * T_SEQ * DK;

    // stage = 128 rows x 128B = 1024 x 16B chunks -> 8 cpa16/thread
#define VISSUE(buf, jj0)                                                        \
    do {                                                                        \
        const uint32_t vb = sVs + (uint32_t)(buf) * VBUFW * 4;                  \
        _Pragma("unroll")                                                       \
        for (int i = 0; i < 8; i++) {                                           \
            const int idx = tid + i * 128;                                      \
            const int j = idx >> 3, cc = idx & 7;                               \
            cpa16(vb + (uint32_t)(j * VST + cc * 4) * 4,                        \
                  &Vp[(size_t)((jj0) + j) * DK + cc * 8]);                      \
        }                                                                       \
    } while (0)

    VISSUE(0, 0);
    cpa_commit();

    const int NCH = T_SEQ / VROWS;   // 16
    for (int kt = 0; kt < NCH; kt++) {
        __syncthreads();   // all warps done reading the buffer about to be refilled
        if (kt + 1 < NCH) VISSUE((kt + 1) & 1, (kt + 1) * VROWS);
        cpa_commit();
        cpa_wait<1>();     // chunk kt's data has landed
        __syncthreads();

        // two 64-key halves, no barrier between them
#pragma unroll
        for (int hh = 0; hh < 2; hh++) {
            const int j0 = kt * VROWS + hh * 64;
            const uint32_t vBase = sVs + (uint32_t)(kt & 1) * VBUFW * 4
                                 + (uint32_t)hh * 64 * VST * 4;

            // S = Qs · V^T
            float s[2][8][4];
#pragma unroll
            for (int mt = 0; mt < 2; mt++)
#pragma unroll
                for (int jt = 0; jt < 8; jt++)
#pragma unroll
                    for (int i = 0; i < 4; i++) s[mt][jt][i] = 0.f;
#pragma unroll
            for (int kd = 0; kd < 4; kd++) {
#pragma unroll
                for (int jp = 0; jp < 4; jp++) {
                    uint32_t b[4];
                    ldsm_x4(vBase + (uint32_t)(jp * 16) * (VST * 4) + sRow + kd * 32, b);
                    mma16(s[0][jp * 2 + 0], qa[kd][0], b[0], b[1]);
                    mma16(s[1][jp * 2 + 0], qa[kd][1], b[0], b[1]);
                    mma16(s[0][jp * 2 + 1], qa[kd][0], b[2], b[3]);
                    mma16(s[1][jp * 2 + 1], qa[kd][1], b[2], b[3]);
                }
            }

            // mask + packed fp16 exp2; P stays in registers (= A-frags for P·V)
            uint32_t pf[2][8][2];
#pragma unroll
            for (int mt = 0; mt < 2; mt++) {
                float sum0 = 0.f, sum1 = 0.f;
#pragma unroll
                for (int jt = 0; jt < 8; jt++) {
                    const float mb0 = Ms[j0 + jt * 8 + t * 2];
                    const float mb1 = Ms[j0 + jt * 8 + t * 2 + 1];
                    const uint32_t pA = h2exp2(s[mt][jt][0] + mb0, s[mt][jt][1] + mb1);
                    const uint32_t pB = h2exp2(s[mt][jt][2] + mb0, s[mt][jt][3] + mb1);
                    pf[mt][jt][0] = pA;
                    pf[mt][jt][1] = pB;
                    const float2 fA = __half22float2(*(const __half2*)&pA);
                    const float2 fB = __half22float2(*(const __half2*)&pB);
                    sum0 += fA.x + fA.y;
                    sum1 += fB.x + fB.y;
                }
                sum0 += __shfl_xor_sync(0xffffffffu, sum0, 1);
                sum0 += __shfl_xor_sync(0xffffffffu, sum0, 2);
                sum1 += __shfl_xor_sync(0xffffffffu, sum1, 1);
                sum1 += __shfl_xor_sync(0xffffffffu, sum1, 2);
                l[mt][0] += sum0;
                l[mt][1] += sum1;
            }

            // O += P · V
#pragma unroll
            for (int kj = 0; kj < 4; kj++) {
                uint32_t a[2][4];
#pragma unroll
                for (int mt = 0; mt < 2; mt++) {
                    a[mt][0] = pf[mt][2 * kj + 0][0];
                    a[mt][1] = pf[mt][2 * kj + 0][1];
                    a[mt][2] = pf[mt][2 * kj + 1][0];
                    a[mt][3] = pf[mt][2 * kj + 1][1];
                }
                const uint32_t kBase = vBase + (uint32_t)(kj * 16) * (VST * 4) + tRow;
#pragma unroll
                for (int dp = 0; dp < 4; dp++) {
                    uint32_t b[4];
                    ldsm_x4t(kBase + dp * 32, b);
                    mma16(o[0][dp * 2 + 0], a[0], b[0], b[1]);
                    mma16(o[1][dp * 2 + 0], a[1], b[0], b[1]);
                    mma16(o[0][dp * 2 + 1], a[0], b[2], b[3]);
                    mma16(o[1][dp * 2 + 1], a[1], b[2], b[3]);
                }
            }
        }
    }
#undef VISSUE

    // epilogue: /l, write fp16 merged [n, t, h*64+d]
#pragma unroll
    for (int mt = 0; mt < 2; mt++) {
        const float il0 = 1.f / l[mt][0], il1 = 1.f / l[mt][1];
        const int t0 = q0 + wr + mt * 16 + g;
        const int t1 = t0 + 8;
#pragma unroll
        for (int dt = 0; dt < 8; dt++) {
            const int d = dt * 8 + t * 2;
            *(uint32_t*)&A[(size_t)((n * T_SEQ + t0) * NHEAD + h) * DK + d] =
                pack_h2(o[mt][dt][0] * il0, o[mt][dt][1] * il0);
            *(uint32_t*)&A[(size_t)((n * T_SEQ + t1) * NHEAD + h) * DK + d] =
                pack_h2(o[mt][dt][2] * il1, o[mt][dt][3] * il1);
        }
    }
}

// ---------------------------------------------------------------------------
// Inputs: 0 x_k, 1 x_v, 2 x_q, 3 mask, 4 Wk, 5 bk, 6 Wv, 7 bv,
//         8 Wq, 9 bq, 10 Wf, 11 bf.  K projection is dead code in reference.
// ---------------------------------------------------------------------------
extern "C" void kernel_launch(void* const* d_in, const int* in_sizes, int n_in,
                              void* d_out, int out_size)
{
    const float* x_v  = (const float*)d_in[1];
    const float* x_q  = (const float*)d_in[2];
    const int*   mask = (const int*)d_in[3];
    const float* Wv   = (const float*)d_in[6];
    const float* bv   = (const float*)d_in[7];
    const float* Wq   = (const float*)d_in[8];
    const float* bq   = (const float*)d_in[9];
    const float* Wf   = (const float*)d_in[10];
    const float* bf   = (const float*)d_in[11];
    float* out = (float*)d_out;

    __half *gQ, *gV, *gA, *gXq, *gXv, *gWqT, *gWvT, *gWfT;
    cudaGetSymbolAddress((void**)&gQ, g_Q);
    cudaGetSymbolAddress((void**)&gV, g_V);
    cudaGetSymbolAddress((void**)&gA, g_A);
    cudaGetSymbolAddress((void**)&gXq, g_Xq);
    cudaGetSymbolAddress((void**)&gXv, g_Xv);
    cudaGetSymbolAddress((void**)&gWqT, g_WqT);
    cudaGetSymbolAddress((void**)&gWvT, g_WvT);
    cudaGetSymbolAddress((void**)&gWfT, g_WfT);

    cudaFuncSetAttribute(gemm_f16, cudaFuncAttributeMaxDynamicSharedMemorySize, GEMM_SMEM);
    cudaFuncSetAttribute(attn_f16, cudaFuncAttributeMaxDynamicSharedMemorySize, ATTN_SMEM);

    const float QSC = 0.18033688f;   // 0.125 * log2(e)

    const int nx4 = NB * T_SEQ * DMODEL / 4;
    cvtX2<<<dim3(nx4 / 256, 2), 256>>>((const float4*)x_q, (const float4*)x_v,
                                       (uint2*)gXq, (uint2*)gXv, nx4);          // 0
    cvtW3<<<dim3(32, 32, 3), dim3(32, 8)>>>(Wq, Wv, Wf, gWqT, gWvT, gWfT);      // 1

    dim3 gg(HDIM / 128, (NB * T_SEQ) / 128);
    gemm_f16<<<gg, 256, GEMM_SMEM>>>(gXq, gWqT, bq, nullptr, gQ, 1, QSC);       // 2
    gemm_f16<<<gg, 256, GEMM_SMEM>>>(gXv, gWvT, bv, nullptr, gV, 1, 1.0f);      // 3
    attn_f16<<<dim3(T_SEQ / 128, NB * NHEAD), 128, ATTN_SMEM>>>(gQ, gV, mask, gA); // 4
    gemm_f16<<<gg, 256, GEMM_SMEM>>>(gA, gWfT, bf, out, nullptr, 0, 1.0f);      // 5
}

// round 14
// speedup vs baseline: 1.1516x; 1.1516x over previous
#include <cuda_runtime.h>
#include <cuda_fp16.h>
#include <cstdint>

#define T_SEQ 2048
#define NB    4
#define NHEAD 16
#define DK    64
#define DMODEL 1024
#define HDIM  1024

// Scratch (allocation-free rule: __device__ globals)
__device__ __half g_Q[NB * NHEAD * T_SEQ * DK];    // [n,h,t,d] fp16, pre-scaled
__device__ __half g_V[NB * NHEAD * T_SEQ * DK];    // [n,h,t,d] fp16
__device__ __half g_A[NB * T_SEQ * HDIM];          // [n,t,h*d] fp16
__device__ __half g_Xq[NB * T_SEQ * DMODEL];       // fp16 inputs
__device__ __half g_Xv[NB * T_SEQ * DMODEL];
__device__ __half g_WqT[DMODEL * HDIM];            // W^T fp16: [n][k]
__device__ __half g_WvT[DMODEL * HDIM];
__device__ __half g_WfT[HDIM * DMODEL];

// ---------------------------------------------------------------------------
// helpers
// ---------------------------------------------------------------------------
__device__ __forceinline__ uint32_t pack_h2(float a, float b) {
    __half2 h = __floats2half2_rn(a, b);
    return *(uint32_t*)&h;
}

// packed fp16 exp2 of two floats: {lo=exp2(lo), hi=exp2(hi)} — 1 MUFU for 2
__device__ __forceinline__ uint32_t h2exp2(float lo, float hi) {
    uint32_t r;
    asm("{\n\t.reg .b32 x;\n\t"
        "cvt.rn.f16x2.f32 x, %2, %1;\n\t"
        "ex2.approx.f16x2 %0, x;\n\t}"
        : "=r"(r) : "f"(lo), "f"(hi));
    return r;
}

__device__ __forceinline__ void mma16(float* c, const uint32_t* a, uint32_t b0, uint32_t b1) {
    asm volatile(
        "mma.sync.aligned.m16n8k16.row.col.f32.f16.f16.f32 "
        "{%0,%1,%2,%3}, {%4,%5,%6,%7}, {%8,%9}, {%0,%1,%2,%3};"
        : "+f"(c[0]), "+f"(c[1]), "+f"(c[2]), "+f"(c[3])
        : "r"(a[0]), "r"(a[1]), "r"(a[2]), "r"(a[3]), "r"(b0), "r"(b1));
}

__device__ __forceinline__ void ldsm_x4(uint32_t addr, uint32_t* r) {
    asm volatile("ldmatrix.sync.aligned.m8n8.x4.shared.b16 {%0,%1,%2,%3}, [%4];"
                 : "=r"(r[0]), "=r"(r[1]), "=r"(r[2]), "=r"(r[3]) : "r"(addr));
}
__device__ __forceinline__ void ldsm_x4t(uint32_t addr, uint32_t* r) {
    asm volatile("ldmatrix.sync.aligned.m8n8.x4.trans.shared.b16 {%0,%1,%2,%3}, [%4];"
                 : "=r"(r[0]), "=r"(r[1]), "=r"(r[2]), "=r"(r[3]) : "r"(addr));
}

__device__ __forceinline__ void cpa16(uint32_t s, const void* g) {
    asm volatile("cp.async.cg.shared.global [%0], [%1], 16;" :: "r"(s), "l"(g));
}
__device__ __forceinline__ void cpa_commit() {
    asm volatile("cp.async.commit_group;" ::: "memory");
}
template <int N>
__device__ __forceinline__ void cpa_wait() {
    asm volatile("cp.async.wait_group %0;" :: "n"(N) : "memory");
}
__device__ __forceinline__ uint32_t sm_u32(const void* p) {
    return (uint32_t)__cvta_generic_to_shared(p);
}

// ---------------------------------------------------------------------------
// prep: fp32 -> fp16 (both inputs in one launch, y selects)
// ---------------------------------------------------------------------------
__global__ void cvtX2(const float4* __restrict__ inq, const float4* __restrict__ inv,
                      uint2* __restrict__ outq, uint2* __restrict__ outv, int n4) {
    const float4* in = blockIdx.y ? inv : inq;
    uint2* out = blockIdx.y ? outv : outq;
    int i = blockIdx.x * blockDim.x + threadIdx.x;
    if (i < n4) {
        float4 v = in[i];
        out[i] = make_uint2(pack_h2(v.x, v.y), pack_h2(v.z, v.w));
    }
}

// out[n][k] = half(in[k][n]); three 1024x1024 matrices selected by blockIdx.z
__global__ __launch_bounds__(256)
void cvtW3(const float* __restrict__ W0, const float* __restrict__ W1,
           const float* __restrict__ W2, __half* __restrict__ O0,
           __half* __restrict__ O1, __half* __restrict__ O2)
{
    const float* in = (blockIdx.z == 0) ? W0 : (blockIdx.z == 1) ? W1 : W2;
    __half* out = (blockIdx.z == 0) ? O0 : (blockIdx.z == 1) ? O1 : O2;
    __shared__ float t[32][33];
    const int x = blockIdx.x * 32 + threadIdx.x;
    const int y0 = blockIdx.y * 32;
#pragma unroll
    for (int i = threadIdx.y; i < 32; i += 8)
        t[i][threadIdx.x] = in[(size_t)(y0 + i) * HDIM + x];
    __syncthreads();
    const int ox = blockIdx.y * 32 + threadIdx.x;
    const int oy0 = blockIdx.x * 32;
#pragma unroll
    for (int i = threadIdx.y; i < 32; i += 8)
        out[(size_t)(oy0 + i) * DMODEL + ox] = __float2half_rn(t[threadIdx.x][i]);
}

// ---------------------------------------------------------------------------
// fp16 GEMM body (m16n8k16), R10 config (proven 66.5us):
// CTA 128x128, 256 threads, 8 warps 4m x 2n, k64 chunks, 3-stage cp.async.
// ---------------------------------------------------------------------------
#define AW 36                       // half2 words per k64 row (32 data + 4 pad)
#define STW (128 * AW)
#define NSTG 3
#define GEMM_SMEM (NSTG * 2 * STW * 4)   // 110592 B

__device__ __forceinline__ void gemm_body(
    const __half* __restrict__ X, const __half* __restrict__ Wt,
    const float* __restrict__ bias, float* __restrict__ Cf,
    __half* __restrict__ Ch, int headsplit, float oscale,
    uint32_t* sm, int bm, int bn)
{
    const int tid = threadIdx.x;
    const int lane = tid & 31;
    const int warp = tid >> 5;
    const int g = lane >> 2;
    const int t = lane & 3;
    const int wm = warp & 3;
    const int wn = warp >> 2;

    const uint32_t sBase = sm_u32(sm);
    const int lrow = (lane & 7) + ((lane >> 3) & 1) * 8;
    const int lcol = (lane >> 4) * 16;
    const uint32_t aOff0 = (uint32_t)((wm * 32 + lrow) * (AW * 4) + lcol);
    const uint32_t aOff1 = aOff0 + 16 * (AW * 4);
    uint32_t bOff[4];
#pragma unroll
    for (int n16 = 0; n16 < 4; n16++)
        bOff[n16] = (uint32_t)((wn * 64 + n16 * 16 + lrow) * (AW * 4) + lcol);

    float c[2][8][4];
#pragma unroll
    for (int mt = 0; mt < 2; mt++)
#pragma unroll
        for (int nt = 0; nt < 8; nt++)
#pragma unroll
            for (int i = 0; i < 4; i++) c[mt][nt][i] = 0.f;

#define ISSUE(stage, kk)                                                        \
    do {                                                                        \
        const uint32_t ab = sBase + (uint32_t)(stage) * 2 * STW * 4;            \
        const uint32_t bb = ab + STW * 4;                                       \
        _Pragma("unroll")                                                       \
        for (int i = 0; i < 4; i++) {                                           \
            const int idx = tid + i * 256;                                      \
            const int r = idx >> 3, h8 = (idx & 7) * 8;                         \
            cpa16(ab + (uint32_t)(r * (AW * 4) + h8 * 2),                       \
                  &X[(size_t)(bm + r) * DMODEL + (kk) + h8]);                   \
            cpa16(bb + (uint32_t)(r * (AW * 4) + h8 * 2),                       \
                  &Wt[(size_t)(bn + r) * DMODEL + (kk) + h8]);                  \
        }                                                                       \
    } while (0)

    ISSUE(0, 0);  cpa_commit();
    ISSUE(1, 64); cpa_commit();
    cpa_wait<1>();
    __syncthreads();

    const int NKT = DMODEL / 64;   // 16
    for (int kt = 0; kt < NKT; kt++) {
        const int cur = kt % NSTG;
        if (kt + 2 < NKT) ISSUE((kt + 2) % NSTG, (kt + 2) * 64);
        cpa_commit();

        const uint32_t aBase = sBase + (uint32_t)cur * 2 * STW * 4;
        const uint32_t bBase = aBase + STW * 4;

#pragma unroll
        for (int c2 = 0; c2 < 2; c2++) {
            const uint32_t co = (uint32_t)c2 * 64;
            uint32_t a[2][2][4], b[2][4][4];
#pragma unroll
            for (int ks = 0; ks < 2; ks++) {
                ldsm_x4(aBase + aOff0 + co + ks * 32, a[ks][0]);
                ldsm_x4(aBase + aOff1 + co + ks * 32, a[ks][1]);
#pragma unroll
                for (int n16 = 0; n16 < 4; n16++)
                    ldsm_x4(bBase + bOff[n16] + co + ks * 32, b[ks][n16]);
            }
#pragma unroll
            for (int ks = 0; ks < 2; ks++)
#pragma unroll
                for (int mt = 0; mt < 2; mt++)
#pragma unroll
                    for (int n16 = 0; n16 < 4; n16++) {
                        mma16(c[mt][n16 * 2 + 0], a[ks][mt], b[ks][n16][0], b[ks][n16][2]);
                        mma16(c[mt][n16 * 2 + 1], a[ks][mt], b[ks][n16][1], b[ks][n16][3]);
                    }
        }
        cpa_wait<1>();
        __syncthreads();
    }
#undef ISSUE

#pragma unroll
    for (int mt = 0; mt < 2; mt++) {
#pragma unroll
        for (int nt = 0; nt < 8; nt++) {
            const int row = bm + wm * 32 + mt * 16 + g;
            const int col = bn + wn * 64 + nt * 8 + t * 2;
            const float b0 = bias[col], b1 = bias[col + 1];
            const float v00 = c[mt][nt][0] + b0, v01 = c[mt][nt][1] + b1;
            const float v10 = c[mt][nt][2] + b0, v11 = c[mt][nt][3] + b1;
            if (!headsplit) {
                *(float2*)&Cf[(size_t)row * HDIM + col] = make_float2(v00, v01);
                *(float2*)&Cf[(size_t)(row + 8) * HDIM + col] = make_float2(v10, v11);
            } else {
                const int h = col >> 6, d = col & 63;
                const int n0 = row >> 11, t0 = row & 2047;
                const int n1 = (row + 8) >> 11, t1 = (row + 8) & 2047;
                *(uint32_t*)&Ch[(size_t)(((n0 * NHEAD + h) * T_SEQ) + t0) * DK + d] =
                    pack_h2(oscale * v00, oscale * v01);
                *(uint32_t*)&Ch[(size_t)(((n1 * NHEAD + h) * T_SEQ) + t1) * DK + d] =
                    pack_h2(oscale * v10, oscale * v11);
            }
        }
    }
}

// Batched Q+V projection: blockIdx.z selects operand set. One launch, one tail.
__global__ __launch_bounds__(256, 2)
void gemm_qv(const __half* __restrict__ Xq, const __half* __restrict__ WqT,
             const float* __restrict__ bq, __half* __restrict__ Q,
             const __half* __restrict__ Xv, const __half* __restrict__ WvT,
             const float* __restrict__ bv, __half* __restrict__ V, float qsc)
{
    extern __shared__ uint32_t sm[];
    const int bm = blockIdx.y * 128;
    const int bn = blockIdx.x * 128;
    if (blockIdx.z == 0)
        gemm_body(Xq, WqT, bq, nullptr, Q, 1, qsc, sm, bm, bn);
    else
        gemm_body(Xv, WvT, bv, nullptr, V, 1, 1.0f, sm, bm, bn);
}

// Output projection
__global__ __launch_bounds__(256, 2)
void gemm_out(const __half* __restrict__ A, const __half* __restrict__ WfT,
              const float* __restrict__ bf, float* __restrict__ out)
{
    extern __shared__ uint32_t sm[];
    gemm_body(A, WfT, bf, out, nullptr, 0, 1.0f, sm,
              blockIdx.y * 128, blockIdx.x * 128);
}

// ---------------------------------------------------------------------------
// Flash attention, fp16 m16n8k16, register-resident P (EXACT R10: proven).
// ---------------------------------------------------------------------------
#define VST 36                        // Vs row stride in half2 words (144B)
#define VBUFW (64 * VST)              // words per V buffer
#define ATTN_SMEM (2 * VBUFW * 4 + T_SEQ * 4)   // 26624 B

__global__ __launch_bounds__(128, 3)
void attn_f16(const __half* __restrict__ Q, const __half* __restrict__ V,
              const int* __restrict__ mask, __half* __restrict__ A)
{
    extern __shared__ uint32_t sm[];
    uint32_t* Vs = sm;                        // [2][64][VST]
    float* Ms = (float*)(Vs + 2 * VBUFW);     // additive mask bias [T_SEQ]

    const int tid = threadIdx.x;
    const int lane = tid & 31;
    const int warp = tid >> 5;
    const int g = lane >> 2;
    const int t = lane & 3;
    const int nh = blockIdx.y;
    const int n = nh >> 4;
    const int h = nh & 15;
    const int q0 = blockIdx.x * 128;
    const int wr = warp * 32;

    const uint32_t sVs = sm_u32(Vs);
    const uint32_t sRow = (uint32_t)((lane >> 4) * 8 + (lane & 7)) * (VST * 4)
                        + ((lane >> 3) & 1) * 16;
    const uint32_t tRow = (uint32_t)(lane & 15) * (VST * 4) + (lane >> 4) * 16;

#pragma unroll
    for (int i = 0; i < 16; i++) {
        const int j = tid + i * 128;
        Ms[j] = mask[n * T_SEQ + j] ? 0.f : -1e30f;
    }

    // Q fragments (already scaled by 0.125*log2e at projection): 4 k16-chunks
    const __half* Qp = Q + ((size_t)nh * T_SEQ + q0 + wr) * DK;
    uint32_t qa[4][2][4];
#pragma unroll
    for (int kd = 0; kd < 4; kd++)
#pragma unroll
        for (int mt = 0; mt < 2; mt++) {
            const int r0 = mt * 16 + g, r1 = r0 + 8;
            qa[kd][mt][0] = *(const uint32_t*)&Qp[r0 * DK + kd * 16 + 2 * t];
            qa[kd][mt][1] = *(const uint32_t*)&Qp[r1 * DK + kd * 16 + 2 * t];
            qa[kd][mt][2] = *(const uint32_t*)&Qp[r0 * DK + kd * 16 + 2 * t + 8];
            qa[kd][mt][3] = *(const uint32_t*)&Qp[r1 * DK + kd * 16 + 2 * t + 8];
        }

    float o[2][8][4];
#pragma unroll
    for (int mt = 0; mt < 2; mt++)
#pragma unroll
        for (int dt = 0; dt < 8; dt++)
#pragma unroll
            for (int i = 0; i < 4; i++) o[mt][dt][i] = 0.f;
    float l[2][2] = {{0.f, 0.f}, {0.f, 0.f}};

    const __half* Vp = V + (size_t)nh * T_SEQ * DK;

#define VISSUE(buf, jj0)                                                        \
    do {                                                                        \
        const uint32_t vb = sVs + (uint32_t)(buf) * VBUFW * 4;                  \
        _Pragma("unroll")                                                       \
        for (int i = 0; i < 4; i++) {                                           \
            const int idx = tid + i * 128;                                      \
            const int j = idx >> 3, cc = idx & 7;                               \
            cpa16(vb + (uint32_t)(j * VST + cc * 4) * 4,                        \
                  &Vp[(size_t)((jj0) + j) * DK + cc * 8]);                      \
        }                                                                       \
    } while (0)

    VISSUE(0, 0);
    cpa_commit();

    const int NCH = T_SEQ / 64;   // 32
    for (int kt = 0; kt < NCH; kt++) {
        const int j0 = kt * 64;
        __syncthreads();
        if (kt + 1 < NCH) VISSUE((kt + 1) & 1, j0 + 64);
        cpa_commit();
        cpa_wait<1>();
        __syncthreads();

        const uint32_t vBase = sVs + (uint32_t)(kt & 1) * VBUFW * 4;

        // S = Qs · V^T
        float s[2][8][4];
#pragma unroll
        for (int mt = 0; mt < 2; mt++)
#pragma unroll
            for (int jt = 0; jt < 8; jt++)
#pragma unroll
                for (int i = 0; i < 4; i++) s[mt][jt][i] = 0.f;
#pragma unroll
        for (int kd = 0; kd < 4; kd++) {
#pragma unroll
            for (int jp = 0; jp < 4; jp++) {
                uint32_t b[4];
                ldsm_x4(vBase + (uint32_t)(jp * 16) * (VST * 4) + sRow + kd * 32, b);
                mma16(s[0][jp * 2 + 0], qa[kd][0], b[0], b[1]);
                mma16(s[1][jp * 2 + 0], qa[kd][1], b[0], b[1]);
                mma16(s[0][jp * 2 + 1], qa[kd][0], b[2], b[3]);
                mma16(s[1][jp * 2 + 1], qa[kd][1], b[2], b[3]);
            }
        }

        // mask + packed fp16 exp2; P stays in registers (= A-frags for P·V)
        uint32_t pf[2][8][2];
#pragma unroll
        for (int mt = 0; mt < 2; mt++) {
            float sum0 = 0.f, sum1 = 0.f;
#pragma unroll
            for (int jt = 0; jt < 8; jt++) {
                const float mb0 = Ms[j0 + jt * 8 + t * 2];
                const float mb1 = Ms[j0 + jt * 8 + t * 2 + 1];
                const uint32_t pA = h2exp2(s[mt][jt][0] + mb0, s[mt][jt][1] + mb1);
                const uint32_t pB = h2exp2(s[mt][jt][2] + mb0, s[mt][jt][3] + mb1);
                pf[mt][jt][0] = pA;
                pf[mt][jt][1] = pB;
                const float2 fA = __half22float2(*(const __half2*)&pA);
                const float2 fB = __half22float2(*(const __half2*)&pB);
                sum0 += fA.x + fA.y;
                sum1 += fB.x + fB.y;
            }
            sum0 += __shfl_xor_sync(0xffffffffu, sum0, 1);
            sum0 += __shfl_xor_sync(0xffffffffu, sum0, 2);
            sum1 += __shfl_xor_sync(0xffffffffu, sum1, 1);
            sum1 += __shfl_xor_sync(0xffffffffu, sum1, 2);
            l[mt][0] += sum0;
            l[mt][1] += sum1;
        }

        // O += P · V
#pragma unroll
        for (int kj = 0; kj < 4; kj++) {
            uint32_t a[2][4];
#pragma unroll
            for (int mt = 0; mt < 2; mt++) {
                a[mt][0] = pf[mt][2 * kj + 0][0];
                a[mt][1] = pf[mt][2 * kj + 0][1];
                a[mt][2] = pf[mt][2 * kj + 1][0];
                a[mt][3] = pf[mt][2 * kj + 1][1];
            }
            const uint32_t kBase = vBase + (uint32_t)(kj * 16) * (VST * 4) + tRow;
#pragma unroll
            for (int dp = 0; dp < 4; dp++) {
                uint32_t b[4];
                ldsm_x4t(kBase + dp * 32, b);
                mma16(o[0][dp * 2 + 0], a[0], b[0], b[1]);
                mma16(o[1][dp * 2 + 0], a[1], b[0], b[1]);
                mma16(o[0][dp * 2 + 1], a[0], b[2], b[3]);
                mma16(o[1][dp * 2 + 1], a[1], b[2], b[3]);
            }
        }
    }
#undef VISSUE

    // epilogue: /l, write fp16 merged [n, t, h*64+d]
#pragma unroll
    for (int mt = 0; mt < 2; mt++) {
        const float il0 = 1.f / l[mt][0], il1 = 1.f / l[mt][1];
        const int t0 = q0 + wr + mt * 16 + g;
        const int t1 = t0 + 8;
#pragma unroll
        for (int dt = 0; dt < 8; dt++) {
            const int d = dt * 8 + t * 2;
            *(uint32_t*)&A[(size_t)((n * T_SEQ + t0) * NHEAD + h) * DK + d] =
                pack_h2(o[mt][dt][0] * il0, o[mt][dt][1] * il0);
            *(uint32_t*)&A[(size_t)((n * T_SEQ + t1) * NHEAD + h) * DK + d] =
                pack_h2(o[mt][dt][2] * il1, o[mt][dt][3] * il1);
        }
    }
}

// ---------------------------------------------------------------------------
// Inputs: 0 x_k, 1 x_v, 2 x_q, 3 mask, 4 Wk, 5 bk, 6 Wv, 7 bv,
//         8 Wq, 9 bq, 10 Wf, 11 bf.  K projection is dead code in reference.
// ---------------------------------------------------------------------------
extern "C" void kernel_launch(void* const* d_in, const int* in_sizes, int n_in,
                              void* d_out, int out_size)
{
    const float* x_v  = (const float*)d_in[1];
    const float* x_q  = (const float*)d_in[2];
    const int*   mask = (const int*)d_in[3];
    const float* Wv   = (const float*)d_in[6];
    const float* bv   = (const float*)d_in[7];
    const float* Wq   = (const float*)d_in[8];
    const float* bq   = (const float*)d_in[9];
    const float* Wf   = (const float*)d_in[10];
    const float* bf   = (const float*)d_in[11];
    float* out = (float*)d_out;

    __half *gQ, *gV, *gA, *gXq, *gXv, *gWqT, *gWvT, *gWfT;
    cudaGetSymbolAddress((void**)&gQ, g_Q);
    cudaGetSymbolAddress((void**)&gV, g_V);
    cudaGetSymbolAddress((void**)&gA, g_A);
    cudaGetSymbolAddress((void**)&gXq, g_Xq);
    cudaGetSymbolAddress((void**)&gXv, g_Xv);
    cudaGetSymbolAddress((void**)&gWqT, g_WqT);
    cudaGetSymbolAddress((void**)&gWvT, g_WvT);
    cudaGetSymbolAddress((void**)&gWfT, g_WfT);

    cudaFuncSetAttribute(gemm_qv, cudaFuncAttributeMaxDynamicSharedMemorySize, GEMM_SMEM);
    cudaFuncSetAttribute(gemm_out, cudaFuncAttributeMaxDynamicSharedMemorySize, GEMM_SMEM);
    cudaFuncSetAttribute(attn_f16, cudaFuncAttributeMaxDynamicSharedMemorySize, ATTN_SMEM);

    const float QSC = 0.18033688f;   // 0.125 * log2(e)

    const int nx4 = NB * T_SEQ * DMODEL / 4;
    cvtX2<<<dim3(nx4 / 256, 2), 256>>>((const float4*)x_q, (const float4*)x_v,
                                       (uint2*)gXq, (uint2*)gXv, nx4);          // 0
    cvtW3<<<dim3(32, 32, 3), dim3(32, 8)>>>(Wq, Wv, Wf, gWqT, gWvT, gWfT);      // 1

    dim3 gqv(HDIM / 128, (NB * T_SEQ) / 128, 2);   // 8 x 64 x 2 = 1024 CTAs
    gemm_qv<<<gqv, 256, GEMM_SMEM>>>(gXq, gWqT, bq, gQ, gXv, gWvT, bv, gV, QSC); // 2
    attn_f16<<<dim3(T_SEQ / 128, NB * NHEAD), 128, ATTN_SMEM>>>(gQ, gV, mask, gA); // 3
    dim3 go(HDIM / 128, (NB * T_SEQ) / 128);
    gemm_out<<<go, 256, GEMM_SMEM>>>(gA, gWfT, bf, out);                        // 4
}

// round 16
// speedup vs baseline: 1.2549x; 1.0897x over previous
#include <cuda_runtime.h>
#include <cuda_fp16.h>
#include <cstdint>

#define T_SEQ 2048
#define NB    4
#define NHEAD 16
#define DK    64
#define DMODEL 1024
#define HDIM  1024

// Scratch (allocation-free rule: __device__ globals)
__device__ __half g_Q[NB * NHEAD * T_SEQ * DK];    // [n,h,t,d] fp16, pre-scaled
__device__ __half g_V[NB * NHEAD * T_SEQ * DK];    // [n,h,t,d] fp16
__device__ __half g_A[NB * T_SEQ * HDIM];          // [n,t,h*d] fp16
__device__ __half g_Xq[NB * T_SEQ * DMODEL];       // fp16 inputs
__device__ __half g_Xv[NB * T_SEQ * DMODEL];
__device__ __half g_WqT[DMODEL * HDIM];            // W^T fp16: [n][k]
__device__ __half g_WvT[DMODEL * HDIM];
__device__ __half g_WfT[HDIM * DMODEL];

// ---------------------------------------------------------------------------
// helpers
// ---------------------------------------------------------------------------
__device__ __forceinline__ uint32_t pack_h2(float a, float b) {
    __half2 h = __floats2half2_rn(a, b);
    return *(uint32_t*)&h;
}

// packed fp16 exp2 of two floats: {lo=exp2(lo), hi=exp2(hi)} — 1 MUFU for 2
__device__ __forceinline__ uint32_t h2exp2(float lo, float hi) {
    uint32_t r;
    asm("{\n\t.reg .b32 x;\n\t"
        "cvt.rn.f16x2.f32 x, %2, %1;\n\t"
        "ex2.approx.f16x2 %0, x;\n\t}"
        : "=r"(r) : "f"(lo), "f"(hi));
    return r;
}

__device__ __forceinline__ void mma16(float* c, const uint32_t* a, uint32_t b0, uint32_t b1) {
    asm volatile(
        "mma.sync.aligned.m16n8k16.row.col.f32.f16.f16.f32 "
        "{%0,%1,%2,%3}, {%4,%5,%6,%7}, {%8,%9}, {%0,%1,%2,%3};"
        : "+f"(c[0]), "+f"(c[1]), "+f"(c[2]), "+f"(c[3])
        : "r"(a[0]), "r"(a[1]), "r"(a[2]), "r"(a[3]), "r"(b0), "r"(b1));
}

__device__ __forceinline__ void ldsm_x4(uint32_t addr, uint32_t* r) {
    asm volatile("ldmatrix.sync.aligned.m8n8.x4.shared.b16 {%0,%1,%2,%3}, [%4];"
                 : "=r"(r[0]), "=r"(r[1]), "=r"(r[2]), "=r"(r[3]) : "r"(addr));
}
__device__ __forceinline__ void ldsm_x4t(uint32_t addr, uint32_t* r) {
    asm volatile("ldmatrix.sync.aligned.m8n8.x4.trans.shared.b16 {%0,%1,%2,%3}, [%4];"
                 : "=r"(r[0]), "=r"(r[1]), "=r"(r[2]), "=r"(r[3]) : "r"(addr));
}

__device__ __forceinline__ void cpa16(uint32_t s, const void* g) {
    asm volatile("cp.async.cg.shared.global [%0], [%1], 16;" :: "r"(s), "l"(g));
}
__device__ __forceinline__ void cpa_commit() {
    asm volatile("cp.async.commit_group;" ::: "memory");
}
template <int N>
__device__ __forceinline__ void cpa_wait() {
    asm volatile("cp.async.wait_group %0;" :: "n"(N) : "memory");
}
__device__ __forceinline__ uint32_t sm_u32(const void* p) {
    return (uint32_t)__cvta_generic_to_shared(p);
}

// ---------------------------------------------------------------------------
// prep: fp32 -> fp16 (both inputs in one launch, y selects)
// ---------------------------------------------------------------------------
__global__ void cvtX2(const float4* __restrict__ inq, const float4* __restrict__ inv,
                      uint2* __restrict__ outq, uint2* __restrict__ outv, int n4) {
    const float4* in = blockIdx.y ? inv : inq;
    uint2* out = blockIdx.y ? outv : outq;
    int i = blockIdx.x * blockDim.x + threadIdx.x;
    if (i < n4) {
        float4 v = in[i];
        out[i] = make_uint2(pack_h2(v.x, v.y), pack_h2(v.z, v.w));
    }
}

// out[n][k] = half(in[k][n]); three 1024x1024 matrices selected by blockIdx.z
__global__ __launch_bounds__(256)
void cvtW3(const float* __restrict__ W0, const float* __restrict__ W1,
           const float* __restrict__ W2, __half* __restrict__ O0,
           __half* __restrict__ O1, __half* __restrict__ O2)
{
    const float* in = (blockIdx.z == 0) ? W0 : (blockIdx.z == 1) ? W1 : W2;
    __half* out = (blockIdx.z == 0) ? O0 : (blockIdx.z == 1) ? O1 : O2;
    __shared__ float t[32][33];
    const int x = blockIdx.x * 32 + threadIdx.x;
    const int y0 = blockIdx.y * 32;
#pragma unroll
    for (int i = threadIdx.y; i < 32; i += 8)
        t[i][threadIdx.x] = in[(size_t)(y0 + i) * HDIM + x];
    __syncthreads();
    const int ox = blockIdx.y * 32 + threadIdx.x;
    const int oy0 = blockIdx.x * 32;
#pragma unroll
    for (int i = threadIdx.y; i < 32; i += 8)
        out[(size_t)(oy0 + i) * DMODEL + ox] = __float2half_rn(t[threadIdx.x][i]);
}

// ---------------------------------------------------------------------------
// fp16 GEMM body (m16n8k16), R10 config (proven 66.5us):
// CTA 128x128, 256 threads, 8 warps 4m x 2n, k64 chunks, 3-stage cp.async.
// ---------------------------------------------------------------------------
#define AW 36                       // half2 words per k64 row (32 data + 4 pad)
#define STW (128 * AW)
#define NSTG 3
#define GEMM_SMEM (NSTG * 2 * STW * 4)   // 110592 B

__device__ __forceinline__ void gemm_body(
    const __half* __restrict__ X, const __half* __restrict__ Wt,
    const float* __restrict__ bias, float* __restrict__ Cf,
    __half* __restrict__ Ch, int headsplit, float oscale,
    uint32_t* sm, int bm, int bn)
{
    const int tid = threadIdx.x;
    const int lane = tid & 31;
    const int warp = tid >> 5;
    const int g = lane >> 2;
    const int t = lane & 3;
    const int wm = warp & 3;
    const int wn = warp >> 2;

    const uint32_t sBase = sm_u32(sm);
    const int lrow = (lane & 7) + ((lane >> 3) & 1) * 8;
    const int lcol = (lane >> 4) * 16;
    const uint32_t aOff0 = (uint32_t)((wm * 32 + lrow) * (AW * 4) + lcol);
    const uint32_t aOff1 = aOff0 + 16 * (AW * 4);
    uint32_t bOff[4];
#pragma unroll
    for (int n16 = 0; n16 < 4; n16++)
        bOff[n16] = (uint32_t)((wn * 64 + n16 * 16 + lrow) * (AW * 4) + lcol);

    float c[2][8][4];
#pragma unroll
    for (int mt = 0; mt < 2; mt++)
#pragma unroll
        for (int nt = 0; nt < 8; nt++)
#pragma unroll
            for (int i = 0; i < 4; i++) c[mt][nt][i] = 0.f;

#define ISSUE(stage, kk)                                                        \
    do {                                                                        \
        const uint32_t ab = sBase + (uint32_t)(stage) * 2 * STW * 4;            \
        const uint32_t bb = ab + STW * 4;                                       \
        _Pragma("unroll")                                                       \
        for (int i = 0; i < 4; i++) {                                           \
            const int idx = tid + i * 256;                                      \
            const int r = idx >> 3, h8 = (idx & 7) * 8;                         \
            cpa16(ab + (uint32_t)(r * (AW * 4) + h8 * 2),                       \
                  &X[(size_t)(bm + r) * DMODEL + (kk) + h8]);                   \
            cpa16(bb + (uint32_t)(r * (AW * 4) + h8 * 2),                       \
                  &Wt[(size_t)(bn + r) * DMODEL + (kk) + h8]);                  \
        }                                                                       \
    } while (0)

    ISSUE(0, 0);  cpa_commit();
    ISSUE(1, 64); cpa_commit();
    cpa_wait<1>();
    __syncthreads();

    const int NKT = DMODEL / 64;   // 16
    for (int kt = 0; kt < NKT; kt++) {
        const int cur = kt % NSTG;
        if (kt + 2 < NKT) ISSUE((kt + 2) % NSTG, (kt + 2) * 64);
        cpa_commit();

        const uint32_t aBase = sBase + (uint32_t)cur * 2 * STW * 4;
        const uint32_t bBase = aBase + STW * 4;

#pragma unroll
        for (int c2 = 0; c2 < 2; c2++) {
            const uint32_t co = (uint32_t)c2 * 64;
            uint32_t a[2][2][4], b[2][4][4];
#pragma unroll
            for (int ks = 0; ks < 2; ks++) {
                ldsm_x4(aBase + aOff0 + co + ks * 32, a[ks][0]);
                ldsm_x4(aBase + aOff1 + co + ks * 32, a[ks][1]);
#pragma unroll
                for (int n16 = 0; n16 < 4; n16++)
                    ldsm_x4(bBase + bOff[n16] + co + ks * 32, b[ks][n16]);
            }
#pragma unroll
            for (int ks = 0; ks < 2; ks++)
#pragma unroll
                for (int mt = 0; mt < 2; mt++)
#pragma unroll
                    for (int n16 = 0; n16 < 4; n16++) {
                        mma16(c[mt][n16 * 2 + 0], a[ks][mt], b[ks][n16][0], b[ks][n16][2]);
                        mma16(c[mt][n16 * 2 + 1], a[ks][mt], b[ks][n16][1], b[ks][n16][3]);
                    }
        }
        cpa_wait<1>();
        __syncthreads();
    }
#undef ISSUE

#pragma unroll
    for (int mt = 0; mt < 2; mt++) {
#pragma unroll
        for (int nt = 0; nt < 8; nt++) {
            const int row = bm + wm * 32 + mt * 16 + g;
            const int col = bn + wn * 64 + nt * 8 + t * 2;
            const float b0 = bias[col], b1 = bias[col + 1];
            const float v00 = c[mt][nt][0] + b0, v01 = c[mt][nt][1] + b1;
            const float v10 = c[mt][nt][2] + b0, v11 = c[mt][nt][3] + b1;
            if (!headsplit) {
                *(float2*)&Cf[(size_t)row * HDIM + col] = make_float2(v00, v01);
                *(float2*)&Cf[(size_t)(row + 8) * HDIM + col] = make_float2(v10, v11);
            } else {
                const int h = col >> 6, d = col & 63;
                const int n0 = row >> 11, t0 = row & 2047;
                const int n1 = (row + 8) >> 11, t1 = (row + 8) & 2047;
                *(uint32_t*)&Ch[(size_t)(((n0 * NHEAD + h) * T_SEQ) + t0) * DK + d] =
                    pack_h2(oscale * v00, oscale * v01);
                *(uint32_t*)&Ch[(size_t)(((n1 * NHEAD + h) * T_SEQ) + t1) * DK + d] =
                    pack_h2(oscale * v10, oscale * v11);
            }
        }
    }
}

// Batched Q+V projection: blockIdx.z selects operand set. One launch, one tail.
__global__ __launch_bounds__(256, 2)
void gemm_qv(const __half* __restrict__ Xq, const __half* __restrict__ WqT,
             const float* __restrict__ bq, __half* __restrict__ Q,
             const __half* __restrict__ Xv, const __half* __restrict__ WvT,
             const float* __restrict__ bv, __half* __restrict__ V, float qsc)
{
    extern __shared__ uint32_t sm[];
    const int bm = blockIdx.y * 128;
    const int bn = blockIdx.x * 128;
    if (blockIdx.z == 0)
        gemm_body(Xq, WqT, bq, nullptr, Q, 1, qsc, sm, bm, bn);
    else
        gemm_body(Xv, WvT, bv, nullptr, V, 1, 1.0f, sm, bm, bn);
}

// Output projection
__global__ __launch_bounds__(256, 2)
void gemm_out(const __half* __restrict__ A, const __half* __restrict__ WfT,
              const float* __restrict__ bf, float* __restrict__ out)
{
    extern __shared__ uint32_t sm[];
    gemm_body(A, WfT, bf, out, nullptr, 0, 1.0f, sm,
              blockIdx.y * 128, blockIdx.x * 128);
}

// ---------------------------------------------------------------------------
// Flash attention, fp16 m16n8k16, register-resident P.
// R15: l-reductions deferred to epilogue (sum commutes with shfl); mask bias
// loaded once per jt as float2 and shared across both mt tiles.
// ---------------------------------------------------------------------------
#define VST 36                        // Vs row stride in half2 words (144B)
#define VBUFW (64 * VST)              // words per V buffer
#define ATTN_SMEM (2 * VBUFW * 4 + T_SEQ * 4)   // 26624 B

__global__ __launch_bounds__(128, 3)
void attn_f16(const __half* __restrict__ Q, const __half* __restrict__ V,
              const int* __restrict__ mask, __half* __restrict__ A)
{
    extern __shared__ uint32_t sm[];
    uint32_t* Vs = sm;                        // [2][64][VST]
    float* Ms = (float*)(Vs + 2 * VBUFW);     // additive mask bias [T_SEQ]

    const int tid = threadIdx.x;
    const int lane = tid & 31;
    const int warp = tid >> 5;
    const int g = lane >> 2;
    const int t = lane & 3;
    const int nh = blockIdx.y;
    const int n = nh >> 4;
    const int h = nh & 15;
    const int q0 = blockIdx.x * 128;
    const int wr = warp * 32;

    const uint32_t sVs = sm_u32(Vs);
    const uint32_t sRow = (uint32_t)((lane >> 4) * 8 + (lane & 7)) * (VST * 4)
                        + ((lane >> 3) & 1) * 16;
    const uint32_t tRow = (uint32_t)(lane & 15) * (VST * 4) + (lane >> 4) * 16;

#pragma unroll
    for (int i = 0; i < 16; i++) {
        const int j = tid + i * 128;
        Ms[j] = mask[n * T_SEQ + j] ? 0.f : -1e30f;
    }

    // Q fragments (already scaled by 0.125*log2e at projection): 4 k16-chunks
    const __half* Qp = Q + ((size_t)nh * T_SEQ + q0 + wr) * DK;
    uint32_t qa[4][2][4];
#pragma unroll
    for (int kd = 0; kd < 4; kd++)
#pragma unroll
        for (int mt = 0; mt < 2; mt++) {
            const int r0 = mt * 16 + g, r1 = r0 + 8;
            qa[kd][mt][0] = *(const uint32_t*)&Qp[r0 * DK + kd * 16 + 2 * t];
            qa[kd][mt][1] = *(const uint32_t*)&Qp[r1 * DK + kd * 16 + 2 * t];
            qa[kd][mt][2] = *(const uint32_t*)&Qp[r0 * DK + kd * 16 + 2 * t + 8];
            qa[kd][mt][3] = *(const uint32_t*)&Qp[r1 * DK + kd * 16 + 2 * t + 8];
        }

    float o[2][8][4];
#pragma unroll
    for (int mt = 0; mt < 2; mt++)
#pragma unroll
        for (int dt = 0; dt < 8; dt++)
#pragma unroll
            for (int i = 0; i < 4; i++) o[mt][dt][i] = 0.f;
    // lane-partial l sums; 4-lane shfl reduction deferred to epilogue
    float l[2][2] = {{0.f, 0.f}, {0.f, 0.f}};

    const __half* Vp = V + (size_t)nh * T_SEQ * DK;

#define VISSUE(buf, jj0)                                                        \
    do {                                                                        \
        const uint32_t vb = sVs + (uint32_t)(buf) * VBUFW * 4;                  \
        _Pragma("unroll")                                                       \
        for (int i = 0; i < 4; i++) {                                           \
            const int idx = tid + i * 128;                                      \
            const int j = idx >> 3, cc = idx & 7;                               \
            cpa16(vb + (uint32_t)(j * VST + cc * 4) * 4,                        \
                  &Vp[(size_t)((jj0) + j) * DK + cc * 8]);                      \
        }                                                                       \
    } while (0)

    VISSUE(0, 0);
    cpa_commit();

    const int NCH = T_SEQ / 64;   // 32
    for (int kt = 0; kt < NCH; kt++) {
        const int j0 = kt * 64;
        __syncthreads();
        if (kt + 1 < NCH) VISSUE((kt + 1) & 1, j0 + 64);
        cpa_commit();
        cpa_wait<1>();
        __syncthreads();

        const uint32_t vBase = sVs + (uint32_t)(kt & 1) * VBUFW * 4;

        // S = Qs · V^T
        float s[2][8][4];
#pragma unroll
        for (int mt = 0; mt < 2; mt++)
#pragma unroll
            for (int jt = 0; jt < 8; jt++)
#pragma unroll
                for (int i = 0; i < 4; i++) s[mt][jt][i] = 0.f;
#pragma unroll
        for (int kd = 0; kd < 4; kd++) {
#pragma unroll
            for (int jp = 0; jp < 4; jp++) {
                uint32_t b[4];
                ldsm_x4(vBase + (uint32_t)(jp * 16) * (VST * 4) + sRow + kd * 32, b);
                mma16(s[0][jp * 2 + 0], qa[kd][0], b[0], b[1]);
                mma16(s[1][jp * 2 + 0], qa[kd][1], b[0], b[1]);
                mma16(s[0][jp * 2 + 1], qa[kd][0], b[2], b[3]);
                mma16(s[1][jp * 2 + 1], qa[kd][1], b[2], b[3]);
            }
        }

        // mask (one float2 LDS per jt, shared across mt) + packed fp16 exp2;
        // P stays in registers (= A-frags for P·V); l accumulated lane-partial
        uint32_t pf[2][8][2];
#pragma unroll
        for (int jt = 0; jt < 8; jt++) {
            const float2 mb = *(const float2*)&Ms[j0 + jt * 8 + t * 2];
#pragma unroll
            for (int mt = 0; mt < 2; mt++) {
                const uint32_t pA = h2exp2(s[mt][jt][0] + mb.x, s[mt][jt][1] + mb.y);
                const uint32_t pB = h2exp2(s[mt][jt][2] + mb.x, s[mt][jt][3] + mb.y);
                pf[mt][jt][0] = pA;
                pf[mt][jt][1] = pB;
                const float2 fA = __half22float2(*(const __half2*)&pA);
                const float2 fB = __half22float2(*(const __half2*)&pB);
                l[mt][0] += fA.x + fA.y;
                l[mt][1] += fB.x + fB.y;
            }
        }

        // O += P · V
#pragma unroll
        for (int kj = 0; kj < 4; kj++) {
            uint32_t a[2][4];
#pragma unroll
            for (int mt = 0; mt < 2; mt++) {
                a[mt][0] = pf[mt][2 * kj + 0][0];
                a[mt][1] = pf[mt][2 * kj + 0][1];
                a[mt][2] = pf[mt][2 * kj + 1][0];
                a[mt][3] = pf[mt][2 * kj + 1][1];
            }
            const uint32_t kBase = vBase + (uint32_t)(kj * 16) * (VST * 4) + tRow;
#pragma unroll
            for (int dp = 0; dp < 4; dp++) {
                uint32_t b[4];
                ldsm_x4t(kBase + dp * 32, b);
                mma16(o[0][dp * 2 + 0], a[0], b[0], b[1]);
                mma16(o[1][dp * 2 + 0], a[1], b[0], b[1]);
                mma16(o[0][dp * 2 + 1], a[0], b[2], b[3]);
                mma16(o[1][dp * 2 + 1], a[1], b[2], b[3]);
            }
        }
    }
#undef VISSUE

    // epilogue: finish l reductions (4-lane groups), /l, write merged output
#pragma unroll
    for (int mt = 0; mt < 2; mt++)
#pragma unroll
        for (int i = 0; i < 2; i++) {
            l[mt][i] += __shfl_xor_sync(0xffffffffu, l[mt][i], 1);
            l[mt][i] += __shfl_xor_sync(0xffffffffu, l[mt][i], 2);
        }
#pragma unroll
    for (int mt = 0; mt < 2; mt++) {
        const float il0 = 1.f / l[mt][0], il1 = 1.f / l[mt][1];
        const int t0 = q0 + wr + mt * 16 + g;
        const int t1 = t0 + 8;
#pragma unroll
        for (int dt = 0; dt < 8; dt++) {
            const int d = dt * 8 + t * 2;
            *(uint32_t*)&A[(size_t)((n * T_SEQ + t0) * NHEAD + h) * DK + d] =
                pack_h2(o[mt][dt][0] * il0, o[mt][dt][1] * il0);
            *(uint32_t*)&A[(size_t)((n * T_SEQ + t1) * NHEAD + h) * DK + d] =
                pack_h2(o[mt][dt][2] * il1, o[mt][dt][3] * il1);
        }
    }
}

// ---------------------------------------------------------------------------
// Inputs: 0 x_k, 1 x_v, 2 x_q, 3 mask, 4 Wk, 5 bk, 6 Wv, 7 bv,
//         8 Wq, 9 bq, 10 Wf, 11 bf.  K projection is dead code in reference.
// ---------------------------------------------------------------------------
extern "C" void kernel_launch(void* const* d_in, const int* in_sizes, int n_in,
                              void* d_out, int out_size)
{
    const float* x_v  = (const float*)d_in[1];
    const float* x_q  = (const float*)d_in[2];
    const int*   mask = (const int*)d_in[3];
    const float* Wv   = (const float*)d_in[6];
    const float* bv   = (const float*)d_in[7];
    const float* Wq   = (const float*)d_in[8];
    const float* bq   = (const float*)d_in[9];
    const float* Wf   = (const float*)d_in[10];
    const float* bf   = (const float*)d_in[11];
    float* out = (float*)d_out;

    __half *gQ, *gV, *gA, *gXq, *gXv, *gWqT, *gWvT, *gWfT;
    cudaGetSymbolAddress((void**)&gQ, g_Q);
    cudaGetSymbolAddress((void**)&gV, g_V);
    cudaGetSymbolAddress((void**)&gA, g_A);
    cudaGetSymbolAddress((void**)&gXq, g_Xq);
    cudaGetSymbolAddress((void**)&gXv, g_Xv);
    cudaGetSymbolAddress((void**)&gWqT, g_WqT);
    cudaGetSymbolAddress((void**)&gWvT, g_WvT);
    cudaGetSymbolAddress((void**)&gWfT, g_WfT);

    cudaFuncSetAttribute(gemm_qv, cudaFuncAttributeMaxDynamicSharedMemorySize, GEMM_SMEM);
    cudaFuncSetAttribute(gemm_out, cudaFuncAttributeMaxDynamicSharedMemorySize, GEMM_SMEM);
    cudaFuncSetAttribute(attn_f16, cudaFuncAttributeMaxDynamicSharedMemorySize, ATTN_SMEM);

    const float QSC = 0.18033688f;   // 0.125 * log2(e)

    const int nx4 = NB * T_SEQ * DMODEL / 4;
    cvtX2<<<dim3(nx4 / 256, 2), 256>>>((const float4*)x_q, (const float4*)x_v,
                                       (uint2*)gXq, (uint2*)gXv, nx4);          // 0
    cvtW3<<<dim3(32, 32, 3), dim3(32, 8)>>>(Wq, Wv, Wf, gWqT, gWvT, gWfT);      // 1

    dim3 gqv(HDIM / 128, (NB * T_SEQ) / 128, 2);   // 1024 CTAs
    gemm_qv<<<gqv, 256, GEMM_SMEM>>>(gXq, gWqT, bq, gQ, gXv, gWvT, bv, gV, QSC); // 2
    attn_f16<<<dim3(T_SEQ / 128, NB * NHEAD), 128, ATTN_SMEM>>>(gQ, gV, mask, gA); // 3
    dim3 go(HDIM / 128, (NB * T_SEQ) / 128);
    gemm_out<<<go, 256, GEMM_SMEM>>>(gA, gWfT, bf, out);                        // 4
}